// round 1
// baseline (speedup 1.0000x reference)
#include <cuda_runtime.h>
#include <cstdint>

#define BATCH 2
#define SEQ 2048
#define HID 1024
#define NHEADS 16
#define HDIM 64

// Scratch for Q/K/V in [B, NH, S, HD] layout (device globals: allocation-free).
__device__ float g_q[BATCH * NHEADS * SEQ * HDIM];
__device__ float g_k[BATCH * NHEADS * SEQ * HDIM];
__device__ float g_v[BATCH * NHEADS * SEQ * HDIM];

__device__ __forceinline__ uint32_t f2tf(float x) {
    uint32_t r;
    asm("cvt.rna.tf32.f32 %0, %1;" : "=r"(r) : "f"(x));
    return r;
}

__device__ __forceinline__ void mma8(float c[4], const uint32_t a[4], const uint32_t b[2]) {
    asm volatile(
        "mma.sync.aligned.m16n8k8.row.col.f32.tf32.tf32.f32 "
        "{%0,%1,%2,%3}, {%4,%5,%6,%7}, {%8,%9}, {%0,%1,%2,%3};\n"
        : "+f"(c[0]), "+f"(c[1]), "+f"(c[2]), "+f"(c[3])
        : "r"(a[0]), "r"(a[1]), "r"(a[2]), "r"(a[3]), "r"(b[0]), "r"(b[1]));
}

// ============================================================================
// QKV projection: C[m,n] = sum_k X[m,k] * W[n,k] + bias[n]
// M=4096, N=1024, K=1024. BM=128, BN=64, BK=32. 256 threads, warps 4(M)x2(N).
// Output scattered to [B, NH, S, HD]; since BN==HD, h == blockIdx.x.
// ============================================================================
__global__ void __launch_bounds__(256) qkv_kernel(
    const float* __restrict__ X,
    const float* __restrict__ Wq, const float* __restrict__ bq,
    const float* __restrict__ Wk, const float* __restrict__ bk,
    const float* __restrict__ Wv, const float* __restrict__ bv)
{
    const int z = blockIdx.z;
    const float* W    = (z == 0) ? Wq : (z == 1) ? Wk : Wv;
    const float* bias = (z == 0) ? bq : (z == 1) ? bk : bv;
    float* out        = (z == 0) ? g_q : (z == 1) ? g_k : g_v;

    __shared__ float As[128 * 36];  // [128][32] + pad 4
    __shared__ float Bs[64 * 36];   // [64][32]  + pad 4

    const int tid  = threadIdx.x;
    const int lane = tid & 31;
    const int warp = tid >> 5;
    const int wm = warp >> 1;       // 0..3
    const int wn = warp & 1;        // 0..1
    const int lr = lane >> 2;       // 0..7
    const int lc = lane & 3;        // 0..3
    const int m0 = blockIdx.y * 128;
    const int n0 = blockIdx.x * 64;

    float acc[2][4][4];
#pragma unroll
    for (int mt = 0; mt < 2; ++mt)
#pragma unroll
        for (int nt = 0; nt < 4; ++nt)
#pragma unroll
            for (int r = 0; r < 4; ++r) acc[mt][nt][r] = 0.0f;

    const uint32_t* Asu = (const uint32_t*)As;
    const uint32_t* Bsu = (const uint32_t*)Bs;

    for (int kt = 0; kt < 32; ++kt) {
        // Load A tile 128x32 (4 float4 per thread)
#pragma unroll
        for (int i = 0; i < 4; ++i) {
            int fi = tid + i * 256;
            int row = fi >> 3;
            int c4 = (fi & 7) * 4;
            float4 v = *(const float4*)(X + (size_t)(m0 + row) * HID + kt * 32 + c4);
            float* dst = As + row * 36 + c4;
            dst[0] = __uint_as_float(f2tf(v.x));
            dst[1] = __uint_as_float(f2tf(v.y));
            dst[2] = __uint_as_float(f2tf(v.z));
            dst[3] = __uint_as_float(f2tf(v.w));
        }
        // Load B tile 64x32 (2 float4 per thread)
#pragma unroll
        for (int i = 0; i < 2; ++i) {
            int fi = tid + i * 256;
            int row = fi >> 3;
            int c4 = (fi & 7) * 4;
            float4 v = *(const float4*)(W + (size_t)(n0 + row) * HID + kt * 32 + c4);
            float* dst = Bs + row * 36 + c4;
            dst[0] = __uint_as_float(f2tf(v.x));
            dst[1] = __uint_as_float(f2tf(v.y));
            dst[2] = __uint_as_float(f2tf(v.z));
            dst[3] = __uint_as_float(f2tf(v.w));
        }
        __syncthreads();

#pragma unroll
        for (int ks = 0; ks < 4; ++ks) {
            uint32_t a[2][4];
#pragma unroll
            for (int mt = 0; mt < 2; ++mt) {
                int rb = wm * 32 + mt * 16;
                a[mt][0] = Asu[(rb + lr) * 36 + ks * 8 + lc];
                a[mt][1] = Asu[(rb + lr + 8) * 36 + ks * 8 + lc];
                a[mt][2] = Asu[(rb + lr) * 36 + ks * 8 + lc + 4];
                a[mt][3] = Asu[(rb + lr + 8) * 36 + ks * 8 + lc + 4];
            }
#pragma unroll
            for (int nt = 0; nt < 4; ++nt) {
                int nb = wn * 32 + nt * 8;
                uint32_t bf[2];
                bf[0] = Bsu[(nb + lr) * 36 + ks * 8 + lc];
                bf[1] = Bsu[(nb + lr) * 36 + ks * 8 + lc + 4];
#pragma unroll
                for (int mt = 0; mt < 2; ++mt) mma8(acc[mt][nt], a[mt], bf);
            }
        }
        __syncthreads();
    }

    // Epilogue: scatter to [B, NH, S, HD]; h == blockIdx.x
    const int h = blockIdx.x;
#pragma unroll
    for (int mt = 0; mt < 2; ++mt) {
#pragma unroll
        for (int nt = 0; nt < 4; ++nt) {
#pragma unroll
            for (int r = 0; r < 4; ++r) {
                int row = wm * 32 + mt * 16 + lr + (r >> 1) * 8;
                int col = wn * 32 + nt * 8 + 2 * lc + (r & 1);
                int m = m0 + row;
                int b = m >> 11;          // /2048
                int s = m & 2047;
                out[(((size_t)b * NHEADS + h) * SEQ + s) * HDIM + col] =
                    acc[mt][nt][r] + bias[n0 + col];
            }
        }
    }
}

// ============================================================================
// Flash attention: per (q-tile of 128, b*h). 256 threads = 8 warps, each warp
// owns 16 q rows. Stream BN=64 k/v tiles. TF32 mma + fp32 online softmax.
// Smem: Qs(128x68, reused as Ps) + Ks(64x68) + Vts(64x68) + mask(64).
// ============================================================================
#define ATTN_SMEM_FLOATS (128 * 68 + 64 * 68 + 64 * 68 + 64)
#define ATTN_SMEM_BYTES (ATTN_SMEM_FLOATS * 4)

__global__ void __launch_bounds__(256, 1) attn_kernel(
    const float* __restrict__ mask, float* __restrict__ out)
{
    extern __shared__ float smem[];
    float* Qs = smem;                    // 128*68, reused as Ps
    float* Ks = smem + 128 * 68;         // 64*68
    float* Vts = Ks + 64 * 68;           // 64*68 (transposed: [d][n])
    float* masks = Vts + 64 * 68;        // 64

    const int tid = threadIdx.x;
    const int lane = tid & 31;
    const int warp = tid >> 5;
    const int lr = lane >> 2;
    const int lc = lane & 3;
    const int wr = warp * 16;            // warp's q-row base within tile

    const int bh = blockIdx.y;           // b*16 + h
    const int b = bh >> 4;
    const int h = bh & 15;
    const int q0 = blockIdx.x * 128;

    const float* qptr = g_q + (size_t)bh * SEQ * HDIM;
    const float* kptr = g_k + (size_t)bh * SEQ * HDIM;
    const float* vptr = g_v + (size_t)bh * SEQ * HDIM;

    // Stage Q tile (128x64) to smem as tf32
#pragma unroll
    for (int i = 0; i < 8; ++i) {
        int fi = tid + i * 256;
        int row = fi >> 4;
        int c4 = (fi & 15) * 4;
        float4 v = *(const float4*)(qptr + (size_t)(q0 + row) * HDIM + c4);
        float* dst = Qs + row * 68 + c4;
        dst[0] = __uint_as_float(f2tf(v.x));
        dst[1] = __uint_as_float(f2tf(v.y));
        dst[2] = __uint_as_float(f2tf(v.z));
        dst[3] = __uint_as_float(f2tf(v.w));
    }
    __syncthreads();

    // Q fragments stay in registers for the whole kernel
    uint32_t qa[8][4];
    {
        const uint32_t* Qsu = (const uint32_t*)Qs;
#pragma unroll
        for (int ks = 0; ks < 8; ++ks) {
            qa[ks][0] = Qsu[(wr + lr) * 68 + ks * 8 + lc];
            qa[ks][1] = Qsu[(wr + lr + 8) * 68 + ks * 8 + lc];
            qa[ks][2] = Qsu[(wr + lr) * 68 + ks * 8 + lc + 4];
            qa[ks][3] = Qsu[(wr + lr + 8) * 68 + ks * 8 + lc + 4];
        }
    }

    float mrow[2] = {-1e30f, -1e30f};
    float lrow[2] = {0.0f, 0.0f};
    float oacc[8][4];
#pragma unroll
    for (int nt = 0; nt < 8; ++nt)
#pragma unroll
        for (int r = 0; r < 4; ++r) oacc[nt][r] = 0.0f;

    const uint32_t* Ksu = (const uint32_t*)Ks;
    const uint32_t* Vtsu = (const uint32_t*)Vts;
    uint32_t* Psu = (uint32_t*)Qs;  // reuse
    const uint32_t* Psc = (const uint32_t*)Qs;

    for (int j = 0; j < 32; ++j) {
        // Load K tile (64x64) and V tile transposed
#pragma unroll
        for (int i = 0; i < 4; ++i) {
            int fi = tid + i * 256;
            int row = fi >> 4;           // n within tile
            int c4 = (fi & 15) * 4;      // d
            float4 kv = *(const float4*)(kptr + (size_t)(j * 64 + row) * HDIM + c4);
            float* kd = Ks + row * 68 + c4;
            kd[0] = __uint_as_float(f2tf(kv.x));
            kd[1] = __uint_as_float(f2tf(kv.y));
            kd[2] = __uint_as_float(f2tf(kv.z));
            kd[3] = __uint_as_float(f2tf(kv.w));
            float4 vv = *(const float4*)(vptr + (size_t)(j * 64 + row) * HDIM + c4);
            Vts[(c4 + 0) * 68 + row] = __uint_as_float(f2tf(vv.x));
            Vts[(c4 + 1) * 68 + row] = __uint_as_float(f2tf(vv.y));
            Vts[(c4 + 2) * 68 + row] = __uint_as_float(f2tf(vv.z));
            Vts[(c4 + 3) * 68 + row] = __uint_as_float(f2tf(vv.w));
        }
        if (tid < 16) {
            float4 mv = *(const float4*)(mask + (size_t)b * SEQ + j * 64 + tid * 4);
            masks[tid * 4 + 0] = mv.x;
            masks[tid * 4 + 1] = mv.y;
            masks[tid * 4 + 2] = mv.z;
            masks[tid * 4 + 3] = mv.w;
        }
        __syncthreads();

        // S = Q @ K^T  (warp: 16 x 64)
        float sacc[8][4];
#pragma unroll
        for (int nt = 0; nt < 8; ++nt)
#pragma unroll
            for (int r = 0; r < 4; ++r) sacc[nt][r] = 0.0f;

#pragma unroll
        for (int ks = 0; ks < 8; ++ks) {
#pragma unroll
            for (int nt = 0; nt < 8; ++nt) {
                uint32_t bf[2];
                bf[0] = Ksu[(nt * 8 + lr) * 68 + ks * 8 + lc];
                bf[1] = Ksu[(nt * 8 + lr) * 68 + ks * 8 + lc + 4];
                mma8(sacc[nt], qa[ks], bf);
            }
        }

        // scale + mask, row max
        float tmax[2] = {-1e30f, -1e30f};
#pragma unroll
        for (int nt = 0; nt < 8; ++nt) {
#pragma unroll
            for (int r = 0; r < 4; ++r) {
                int col = nt * 8 + 2 * lc + (r & 1);
                float v = sacc[nt][r] * 0.125f + masks[col];
                sacc[nt][r] = v;
                int ri = r >> 1;
                tmax[ri] = fmaxf(tmax[ri], v);
            }
        }
#pragma unroll
        for (int ri = 0; ri < 2; ++ri) {
            tmax[ri] = fmaxf(tmax[ri], __shfl_xor_sync(0xffffffffu, tmax[ri], 1));
            tmax[ri] = fmaxf(tmax[ri], __shfl_xor_sync(0xffffffffu, tmax[ri], 2));
        }

        float alpha[2], psum[2] = {0.0f, 0.0f};
#pragma unroll
        for (int ri = 0; ri < 2; ++ri) {
            float mnew = fmaxf(mrow[ri], tmax[ri]);
            alpha[ri] = __expf(mrow[ri] - mnew);
            mrow[ri] = mnew;
        }

        // P = exp(S - m), write to Ps (tf32), accumulate row sums
#pragma unroll
        for (int nt = 0; nt < 8; ++nt) {
#pragma unroll
            for (int r = 0; r < 4; ++r) {
                int ri = r >> 1;
                float p = __expf(sacc[nt][r] - mrow[ri]);
                psum[ri] += p;
                int row = wr + lr + ri * 8;
                int col = nt * 8 + 2 * lc + (r & 1);
                Psu[row * 68 + col] = f2tf(p);
            }
        }
#pragma unroll
        for (int ri = 0; ri < 2; ++ri) {
            psum[ri] += __shfl_xor_sync(0xffffffffu, psum[ri], 1);
            psum[ri] += __shfl_xor_sync(0xffffffffu, psum[ri], 2);
            lrow[ri] = lrow[ri] * alpha[ri] + psum[ri];
        }
        // rescale O
#pragma unroll
        for (int nt = 0; nt < 8; ++nt)
#pragma unroll
            for (int r = 0; r < 4; ++r) oacc[nt][r] *= alpha[r >> 1];

        __syncwarp();

        // O += P @ V  (k = 64 score cols; nt tiles over d)
#pragma unroll
        for (int ks = 0; ks < 8; ++ks) {
            uint32_t pa[4];
            pa[0] = Psc[(wr + lr) * 68 + ks * 8 + lc];
            pa[1] = Psc[(wr + lr + 8) * 68 + ks * 8 + lc];
            pa[2] = Psc[(wr + lr) * 68 + ks * 8 + lc + 4];
            pa[3] = Psc[(wr + lr + 8) * 68 + ks * 8 + lc + 4];
#pragma unroll
            for (int nt = 0; nt < 8; ++nt) {
                uint32_t bf[2];
                bf[0] = Vtsu[(nt * 8 + lr) * 68 + ks * 8 + lc];
                bf[1] = Vtsu[(nt * 8 + lr) * 68 + ks * 8 + lc + 4];
                mma8(oacc[nt], pa, bf);
            }
        }
        __syncthreads();
    }

    // Final normalize + write [B, S, H] output
    float inv[2] = {1.0f / lrow[0], 1.0f / lrow[1]};
#pragma unroll
    for (int nt = 0; nt < 8; ++nt) {
#pragma unroll
        for (int r = 0; r < 4; ++r) {
            int ri = r >> 1;
            int row = wr + lr + ri * 8;
            int col = nt * 8 + 2 * lc + (r & 1);
            out[((size_t)b * SEQ + q0 + row) * HID + h * HDIM + col] =
                oacc[nt][r] * inv[ri];
        }
    }
}

extern "C" void kernel_launch(void* const* d_in, const int* in_sizes, int n_in,
                              void* d_out, int out_size)
{
    const float* hs   = (const float*)d_in[0];
    const float* mask = (const float*)d_in[1];
    const float* Wq   = (const float*)d_in[2];
    const float* bq   = (const float*)d_in[3];
    const float* Wk   = (const float*)d_in[4];
    const float* bk   = (const float*)d_in[5];
    const float* Wv   = (const float*)d_in[6];
    const float* bv   = (const float*)d_in[7];
    float* out = (float*)d_out;

    dim3 gq(HID / 64, (BATCH * SEQ) / 128, 3);   // (16, 32, 3)
    qkv_kernel<<<gq, 256>>>(hs, Wq, bq, Wk, bk, Wv, bv);

    cudaFuncSetAttribute(attn_kernel, cudaFuncAttributeMaxDynamicSharedMemorySize,
                         ATTN_SMEM_BYTES);
    dim3 ga(SEQ / 128, BATCH * NHEADS);          // (16, 32)
    attn_kernel<<<ga, 256, ATTN_SMEM_BYTES>>>(mask, out);
}